// round 6
// baseline (speedup 1.0000x reference)
#include <cuda_runtime.h>
#include <math.h>

#define E_    4
#define C_    64
#define HID_  128
#define B_    16
#define HW_   16384      // 128*128
#define TP    128        // pixels per tile
#define BN_EPS_ 1e-5f

// ---------------- device scratch (no allocs allowed) ----------------
__device__ float g_W1T[E_*C_*HID_];     // [e][c][o]   (BN scale folded)
__device__ float g_t1 [E_*HID_];        // fused bias layer1
__device__ float g_W2T[E_*HID_*HID_];   // [e][i][o]   (BN scale folded)
__device__ float g_t2 [E_*HID_];
__device__ float g_W3T[E_*HID_*C_];     // [e][i][ch]
__device__ float g_gap[B_*C_];
__device__ int   g_sel [B_*2];
__device__ float g_selw[B_*2];

// ---------------- kernel 1: global average pool ----------------
__global__ void gap_kernel(const float* __restrict__ x) {
    int bc = blockIdx.x;                       // 0 .. B*C-1
    const float4* p = (const float4*)(x + (size_t)bc * HW_);
    float s = 0.f;
    for (int i = threadIdx.x; i < HW_/4; i += 256) {
        float4 v = p[i];
        s += v.x + v.y + v.z + v.w;
    }
    __shared__ float red[256];
    red[threadIdx.x] = s;
    __syncthreads();
    for (int off = 128; off > 0; off >>= 1) {
        if (threadIdx.x < off) red[threadIdx.x] += red[threadIdx.x + off];
        __syncthreads();
    }
    if (threadIdx.x == 0) g_gap[bc] = red[0] * (1.f / HW_);
}

// ---------------- kernel 2: gate (softmax, top-2, renorm, aux loss) ----------------
__global__ void gate_kernel(const float* __restrict__ gw, const float* __restrict__ gb,
                            float* __restrict__ aux_out, int has_aux) {
    __shared__ int   sel_s[B_][2];
    __shared__ float w_s[B_][2];
    int lane = threadIdx.x;
    if (lane < B_) {
        float l[E_];
        #pragma unroll
        for (int e = 0; e < E_; e++) {
            float s = gb[e];
            for (int c = 0; c < C_; c++) s += g_gap[lane*C_ + c] * gw[e*C_ + c];
            l[e] = s;
        }
        float m = l[0];
        #pragma unroll
        for (int e = 1; e < E_; e++) m = fmaxf(m, l[e]);
        float p[E_], sum = 0.f;
        #pragma unroll
        for (int e = 0; e < E_; e++) { p[e] = expf(l[e] - m); sum += p[e]; }
        #pragma unroll
        for (int e = 0; e < E_; e++) p[e] /= sum;
        // top-2 with first-occurrence tie-break (matches jax.lax.top_k)
        int i1 = 0;
        #pragma unroll
        for (int e = 1; e < E_; e++) if (p[e] > p[i1]) i1 = e;
        int i2 = -1;
        #pragma unroll
        for (int e = 0; e < E_; e++) {
            if (e == i1) continue;
            if (i2 < 0 || p[e] > p[i2]) i2 = e;
        }
        float denom = p[i1] + p[i2] + 1e-8f;
        float w1 = p[i1] / denom, w2 = p[i2] / denom;
        g_sel[lane*2]  = i1;  g_sel[lane*2+1]  = i2;
        g_selw[lane*2] = w1;  g_selw[lane*2+1] = w2;
        sel_s[lane][0] = i1;  sel_s[lane][1] = i2;
        w_s[lane][0] = w1;    w_s[lane][1] = w2;
    }
    __syncthreads();
    if (lane == 0 && has_aux) {
        float usage[E_] = {0.f, 0.f, 0.f, 0.f};
        for (int b = 0; b < B_; b++) {        // deterministic serial sum
            usage[sel_s[b][0]] += w_s[b][0];
            usage[sel_s[b][1]] += w_s[b][1];
        }
        float mean = 0.f;
        #pragma unroll
        for (int e = 0; e < E_; e++) mean += usage[e];
        mean *= 0.25f;
        float var = 0.f;
        #pragma unroll
        for (int e = 0; e < E_; e++) { float d = usage[e] - mean; var += d * d; }
        var *= 0.25f;
        aux_out[0] = var / (mean * mean + 1e-10f);
    }
}

// ---------------- kernel 3: weight transpose + BN fold ----------------
__global__ void prep_kernel(const float* __restrict__ W1, const float* __restrict__ b1,
                            const float* __restrict__ g1, const float* __restrict__ be1,
                            const float* __restrict__ m1, const float* __restrict__ v1,
                            const float* __restrict__ W2, const float* __restrict__ b2,
                            const float* __restrict__ g2, const float* __restrict__ be2,
                            const float* __restrict__ m2, const float* __restrict__ v2,
                            const float* __restrict__ W3) {
    int idx = blockIdx.x * 256 + threadIdx.x;     // launched with >= E*HID*HID threads
    if (idx < E_*HID_*HID_) {                     // W2T: [e][o][i] -> [e][i][o] * inv2
        int e = idx / (HID_*HID_);
        int r = idx - e*HID_*HID_;
        int o = r / HID_, i = r % HID_;
        float inv = g2[e*HID_+o] / sqrtf(v2[e*HID_+o] + BN_EPS_);
        g_W2T[(e*HID_ + i)*HID_ + o] = W2[idx] * inv;
    }
    if (idx < E_*HID_*C_) {                       // W1T: [e][o][c] -> [e][c][o] * inv1
        int e = idx / (HID_*C_);
        int r = idx - e*HID_*C_;
        int o = r / C_, c = r % C_;
        float inv = g1[e*HID_+o] / sqrtf(v1[e*HID_+o] + BN_EPS_);
        g_W1T[(e*C_ + c)*HID_ + o] = W1[idx] * inv;
    }
    if (idx < E_*C_*HID_) {                       // W3T: [e][ch][i] -> [e][i][ch]
        int e = idx / (C_*HID_);
        int r = idx - e*C_*HID_;
        int ch = r / HID_, i = r % HID_;
        g_W3T[(e*HID_ + i)*C_ + ch] = W3[idx];
    }
    if (idx < E_*HID_) {                          // fused biases
        float inv1 = g1[idx] / sqrtf(v1[idx] + BN_EPS_);
        g_t1[idx] = (b1[idx] - m1[idx]) * inv1 + be1[idx];
        float inv2 = g2[idx] / sqrtf(v2[idx] + BN_EPS_);
        g_t2[idx] = (b2[idx] - m2[idx]) * inv2 + be2[idx];
    }
}

// ---------------- main fused 3-layer MoE kernel ----------------
#define LOAD_F4(dst, src) { float4 _t = *(const float4*)(src); \
    (dst)[0]=_t.x; (dst)[1]=_t.y; (dst)[2]=_t.z; (dst)[3]=_t.w; }

// 128xTP output GEMM: A (smem, K rows, pitch HID_, M contiguous), B (smem, K rows, pitch TP)
template<int K>
__device__ __forceinline__ void gemm128(const float* __restrict__ A,
                                        const float* __restrict__ Bm,
                                        float* __restrict__ Hout,
                                        const float* __restrict__ bias,
                                        int tx, int ty) {
    float acc[8][8];
    #pragma unroll
    for (int m = 0; m < 8; m++)
        #pragma unroll
        for (int n = 0; n < 8; n++) acc[m][n] = 0.f;

    #pragma unroll 4
    for (int k = 0; k < K; k++) {
        float a[8], bb[8];
        LOAD_F4(a,     &A[k*HID_ + ty*8]);
        LOAD_F4(a + 4, &A[k*HID_ + ty*8 + 4]);
        LOAD_F4(bb,     &Bm[k*TP + tx*8]);
        LOAD_F4(bb + 4, &Bm[k*TP + tx*8 + 4]);
        #pragma unroll
        for (int m = 0; m < 8; m++)
            #pragma unroll
            for (int n = 0; n < 8; n++)
                acc[m][n] = fmaf(a[m], bb[n], acc[m][n]);
    }
    #pragma unroll
    for (int m = 0; m < 8; m++) {
        int o = ty*8 + m;
        float bv = bias[o];
        float4 r0, r1;
        r0.x = fmaxf(acc[m][0] + bv, 0.f);
        r0.y = fmaxf(acc[m][1] + bv, 0.f);
        r0.z = fmaxf(acc[m][2] + bv, 0.f);
        r0.w = fmaxf(acc[m][3] + bv, 0.f);
        r1.x = fmaxf(acc[m][4] + bv, 0.f);
        r1.y = fmaxf(acc[m][5] + bv, 0.f);
        r1.z = fmaxf(acc[m][6] + bv, 0.f);
        r1.w = fmaxf(acc[m][7] + bv, 0.f);
        *(float4*)&Hout[o*TP + tx*8]     = r0;
        *(float4*)&Hout[o*TP + tx*8 + 4] = r1;
    }
}

__global__ void __launch_bounds__(256, 1)
moe_main(const float* __restrict__ x, const float* __restrict__ b3,
         float* __restrict__ out) {
    extern __shared__ float sm[];
    float* Xs = sm;                    // 64 * 128
    float* Ws = Xs + C_*TP;            // up to 128 * 128
    float* H1 = Ws + HID_*HID_;        // 128 * 128
    float* H2 = H1 + HID_*TP;          // 128 * 128

    const int tid = threadIdx.x;
    const int tx  = tid & 15;
    const int ty  = tid >> 4;
    const int b   = blockIdx.y;
    const int p0  = blockIdx.x * TP;

    // ---- load X tile: Xs[c][p] (coalesced float4) ----
    {
        const float4* xg = (const float4*)(x + (size_t)b * C_ * HW_);
        int base4 = p0 >> 2;
        #pragma unroll
        for (int i = tid; i < C_*TP/4; i += 256) {
            int c = i >> 5;            // TP/4 = 32 float4 per row
            int j = i & 31;
            ((float4*)Xs)[i] = xg[(size_t)c*(HW_/4) + base4 + j];
        }
    }

    float oacc[4][8];
    #pragma unroll
    for (int m = 0; m < 4; m++)
        #pragma unroll
        for (int n = 0; n < 8; n++) oacc[m][n] = 0.f;

    #pragma unroll 1
    for (int s = 0; s < 2; s++) {
        int   e    = g_sel[b*2 + s];
        float gwgt = g_selw[b*2 + s];

        __syncthreads();   // protect Ws/H2 reads from previous iteration; X load done
        // ---- stage W1T (C_*HID_ floats = 32KB) ----
        {
            const float4* wg = (const float4*)(g_W1T + e*C_*HID_);
            for (int i = tid; i < C_*HID_/4; i += 256) ((float4*)Ws)[i] = wg[i];
        }
        __syncthreads();
        // ---- layer 1: H1 = relu(W1s @ X + t1) ----
        gemm128<C_>(Ws, Xs, H1, g_t1 + e*HID_, tx, ty);
        __syncthreads();
        // ---- stage W2T (HID_*HID_ floats = 64KB) ----
        {
            const float4* wg = (const float4*)(g_W2T + e*HID_*HID_);
            for (int i = tid; i < HID_*HID_/4; i += 256) ((float4*)Ws)[i] = wg[i];
        }
        __syncthreads();
        // ---- layer 2: H2 = relu(W2s @ H1 + t2) ----
        gemm128<HID_>(Ws, H1, H2, g_t2 + e*HID_, tx, ty);
        __syncthreads();
        // ---- stage W3T (HID_*C_ floats = 32KB) ----
        {
            const float4* wg = (const float4*)(g_W3T + e*HID_*C_);
            for (int i = tid; i < HID_*C_/4; i += 256) ((float4*)Ws)[i] = wg[i];
        }
        __syncthreads();
        // ---- layer 3: oacc += gwgt * (W3 @ H2 + b3) ----
        {
            float acc[4][8];
            #pragma unroll
            for (int m = 0; m < 4; m++)
                #pragma unroll
                for (int n = 0; n < 8; n++) acc[m][n] = 0.f;

            #pragma unroll 4
            for (int k = 0; k < HID_; k++) {
                float a[4], bb[8];
                LOAD_F4(a,      &Ws[k*C_ + ty*4]);
                LOAD_F4(bb,     &H2[k*TP + tx*8]);
                LOAD_F4(bb + 4, &H2[k*TP + tx*8 + 4]);
                #pragma unroll
                for (int m = 0; m < 4; m++)
                    #pragma unroll
                    for (int n = 0; n < 8; n++)
                        acc[m][n] = fmaf(a[m], bb[n], acc[m][n]);
            }
            const float* b3p = b3 + e*C_;
            #pragma unroll
            for (int m = 0; m < 4; m++) {
                float bias = b3p[ty*4 + m];
                #pragma unroll
                for (int n = 0; n < 8; n++)
                    oacc[m][n] = fmaf(gwgt, acc[m][n] + bias, oacc[m][n]);
            }
        }
    }

    // ---- store output tile: out[b][ch][p0 + ...] ----
    float* og = out + (size_t)b * C_ * HW_ + p0;
    #pragma unroll
    for (int m = 0; m < 4; m++) {
        int ch = ty*4 + m;
        float4 r0, r1;
        r0.x = oacc[m][0]; r0.y = oacc[m][1]; r0.z = oacc[m][2]; r0.w = oacc[m][3];
        r1.x = oacc[m][4]; r1.y = oacc[m][5]; r1.z = oacc[m][6]; r1.w = oacc[m][7];
        *(float4*)&og[(size_t)ch*HW_ + tx*8]     = r0;
        *(float4*)&og[(size_t)ch*HW_ + tx*8 + 4] = r1;
    }
}

// ---------------- launch ----------------
extern "C" void kernel_launch(void* const* d_in, const int* in_sizes, int n_in,
                              void* d_out, int out_size) {
    const float* x   = (const float*)d_in[0];
    const float* W1  = (const float*)d_in[1];
    const float* b1  = (const float*)d_in[2];
    const float* g1  = (const float*)d_in[3];
    const float* be1 = (const float*)d_in[4];
    const float* m1  = (const float*)d_in[5];
    const float* v1  = (const float*)d_in[6];
    const float* W2  = (const float*)d_in[7];
    const float* b2  = (const float*)d_in[8];
    const float* g2  = (const float*)d_in[9];
    const float* be2 = (const float*)d_in[10];
    const float* m2  = (const float*)d_in[11];
    const float* v2  = (const float*)d_in[12];
    const float* W3  = (const float*)d_in[13];
    const float* b3  = (const float*)d_in[14];
    const float* gw  = (const float*)d_in[15];
    const float* gb  = (const float*)d_in[16];
    float* out = (float*)d_out;

    const int SMEM = (C_*TP + 3*HID_*HID_) * 4;    // 229376 bytes
    cudaFuncSetAttribute(moe_main, cudaFuncAttributeMaxDynamicSharedMemorySize, SMEM);

    gap_kernel<<<B_*C_, 256>>>(x);

    prep_kernel<<<(E_*HID_*HID_ + 255) / 256, 256>>>(
        W1, b1, g1, be1, m1, v1, W2, b2, g2, be2, m2, v2, W3);

    const int N = B_ * C_ * HW_;
    int has_aux = (out_size > N) ? 1 : 0;
    gate_kernel<<<1, 32>>>(gw, gb, out + N, has_aux);

    dim3 grid(HW_ / TP, B_);
    moe_main<<<grid, 256, SMEM>>>(x, b3, out);
}